// round 3
// baseline (speedup 1.0000x reference)
#include <cuda_runtime.h>

#define S_GRID 28
#define SS 784            // 28*28
#define NC 80
#define BB 2
#define MAXB 50
#define PRED_C 90         // BB*5 + NC
#define SPLIT 2

__device__ float g_partial[8192];
__device__ int   g_count = 0;

__global__ __launch_bounds__(256) void yolo_loss_kernel(
    const float* __restrict__ pred,
    const float* __restrict__ tgt,
    float* __restrict__ out,
    int batch)
{
    const int bid  = blockIdx.x;
    const int b    = bid >> 1;        // batch index
    const int half = bid & 1;         // which half of the work
    const int tid  = threadIdx.x;
    const float cell = 1.0f / 28.0f;
    const float* pb = pred + (size_t)b * SS * PRED_C;

    __shared__ int    s_cell[MAXB];   // -1 = invalid target
    __shared__ float  s_best[MAXB];
    __shared__ int    s_bestj[MAXB];
    __shared__ float4 s_box[MAXB];    // cx_rel, cy_rel, w, h
    __shared__ int    s_cid[MAXB];
    __shared__ unsigned char s_win[MAXB];
    __shared__ int    s_obj[MAXB];    // compacted winner target indices (all)
    __shared__ int    s_nobj;
    __shared__ int    s_my[MAXB];     // winners owned by this half
    __shared__ unsigned s_mask[MAXB][3];
    __shared__ float  s_red[8];

    // ---- issue target loads ASAP ----
    float tcls = -1.f, tcx = 0.f, tcy = 0.f, tw = 0.f, th = 0.f;
    if (tid < MAXB) {
        const float* tt = tgt + ((size_t)b * MAXB + tid) * 5;
        tcls = __ldg(tt + 0); tcx = __ldg(tt + 1); tcy = __ldg(tt + 2);
        tw   = __ldg(tt + 3); th  = __ldg(tt + 4);
    }

    // ---- noobj conf sweep over this half's cells (fully independent) ----
    float acc_noobj = 0.0f;
    const int cbase = half * (SS / SPLIT);        // 392 cells per half
    #pragma unroll
    for (int k = 0; k < 2; k++) {
        int c = tid + k * 256;
        if (c < SS / SPLIT) {
            const float* pp = pb + (size_t)(cbase + c) * PRED_C;
            float a = __ldg(pp + 4), d = __ldg(pp + 9);
            acc_noobj += a * a + d * d;
        }
    }

    // ---- per-target precompute (dependent: target -> cell -> pred row) ----
    if (tid < MAXB) {
        if (tcls >= 0.0f) {
            int ci  = min(max((int)tcls, 0), NC - 1);
            int col = min((int)(tcx / cell), S_GRID - 1);
            int row = min((int)(tcy / cell), S_GRID - 1);
            int cc  = row * S_GRID + col;
            s_cell[tid] = cc;
            s_cid[tid]  = ci;
            s_box[tid]  = make_float4(tcx / cell - (float)col,
                                      tcy / cell - (float)row, tw, th);
            const float* pp = pb + (size_t)cc * PRED_C;
            float gx1 = tcx - tw * 0.5f, gy1 = tcy - th * 0.5f;
            float gx2 = tcx + tw * 0.5f, gy2 = tcy + th * 0.5f;
            float garea = fmaxf(gx2 - gx1, 0.f) * fmaxf(gy2 - gy1, 0.f);
            float iou[2];
            #pragma unroll
            for (int j = 0; j < 2; j++) {
                float px = (__ldg(pp + 5*j + 0) + (float)col) * cell;
                float py = (__ldg(pp + 5*j + 1) + (float)row) * cell;
                float pw = __ldg(pp + 5*j + 2), ph = __ldg(pp + 5*j + 3);
                float px1 = px - pw * .5f, py1 = py - ph * .5f;
                float px2 = px + pw * .5f, py2 = py + ph * .5f;
                float iw = fmaxf(fminf(px2, gx2) - fmaxf(px1, gx1), 0.f);
                float ih = fmaxf(fminf(py2, gy2) - fmaxf(py1, gy1), 0.f);
                float inter = iw * ih;
                float uni = fmaxf(px2 - px1, 0.f) * fmaxf(py2 - py1, 0.f)
                          + garea - inter;
                iou[j] = inter / (uni + 1e-6f);
            }
            s_bestj[tid] = (iou[1] > iou[0]) ? 1 : 0;   // first-index tie
            s_best[tid]  = fmaxf(iou[0], iou[1]);
        } else {
            s_cell[tid] = -1;
        }
    }
    __syncthreads();

    // ---- winner per cell: first index achieving the max best (scan semantics) ----
    if (tid < MAXB) {
        bool win = (s_cell[tid] >= 0);
        if (win) {
            int myc = s_cell[tid]; float myb = s_best[tid];
            #pragma unroll 5
            for (int s = 0; s < MAXB; s++) {
                if (s == tid || s_cell[s] != myc) continue;
                float ob = s_best[s];
                if (ob > myb || (ob == myb && s < tid)) { win = false; break; }
            }
        }
        s_win[tid] = win ? 1 : 0;
    }
    __syncthreads();

    // ---- deterministic compaction of winners (warp 0, two ballots) ----
    if (tid < 32) {
        unsigned lt = (1u << tid) - 1u;
        bool p0 = s_win[tid] != 0;
        unsigned m0 = __ballot_sync(0xffffffffu, p0);
        if (p0) s_obj[__popc(m0 & lt)] = tid;
        int c0 = __popc(m0);
        bool p1 = (tid < MAXB - 32) && (s_win[32 + tid] != 0);
        unsigned m1 = __ballot_sync(0xffffffffu, p1);
        if (p1) s_obj[c0 + __popc(m1 & lt)] = 32 + tid;
        if (tid == 0) s_nobj = c0 + __popc(m1);
    }
    __syncthreads();
    const int nobj = s_nobj;
    const int nmy  = (nobj > half) ? (nobj - half + SPLIT - 1) / SPLIT : 0;

    // ---- my-half winner list + per-cell class masks ----
    if (tid < MAXB) {
        int gi = half + tid * SPLIT;
        if (gi < nobj) {
            int t = s_obj[gi];
            s_my[tid] = t;
            int myc = s_cell[t];
            unsigned m0 = 0u, m1 = 0u, m2 = 0u;
            for (int s = 0; s < MAXB; s++) {
                if (s_cell[s] == myc) {
                    int ci = s_cid[s];
                    if (ci < 32)      m0 |= 1u << ci;
                    else if (ci < 64) m1 |= 1u << (ci - 32);
                    else              m2 |= 1u << (ci - 64);
                }
            }
            s_mask[tid][0] = m0; s_mask[tid][1] = m1; s_mask[tid][2] = m2;
        }
    }
    __syncthreads();

    float acc_obj = 0.0f, acc_coord = 0.0f, acc_cls = 0.0f;

    // ---- CIoU + obj conf + noobj correction for my obj cells ----
    for (int i = tid; i < nmy; i += 256) {
        int t = s_my[i];
        int c = s_cell[t];
        const float* pp = pb + (size_t)c * PRED_C;
        int r = s_bestj[t];
        float bx = __ldg(pp + 5*r + 0), by = __ldg(pp + 5*r + 1);
        float bw = __ldg(pp + 5*r + 2), bh = __ldg(pp + 5*r + 3);
        float bc = __ldg(pp + 5*r + 4);
        acc_noobj -= bc * bc;                  // responsible box excluded
        float d = bc - s_best[t];
        acc_obj += d * d;

        int row = c / S_GRID, col = c % S_GRID;
        float4 g = s_box[t];
        float px = (bx + (float)col) * cell, py = (by + (float)row) * cell;
        float pw = fabsf(bw), ph = fabsf(bh);
        float gx = (g.x + (float)col) * cell, gy = (g.y + (float)row) * cell;
        float gw = g.z, gh = g.w;

        float px1 = px - pw * .5f, py1 = py - ph * .5f;
        float px2 = px + pw * .5f, py2 = py + ph * .5f;
        float gx1 = gx - gw * .5f, gy1 = gy - gh * .5f;
        float gx2 = gx + gw * .5f, gy2 = gy + gh * .5f;
        float iw = fmaxf(fminf(px2, gx2) - fmaxf(px1, gx1), 0.f);
        float ih = fmaxf(fminf(py2, gy2) - fmaxf(py1, gy1), 0.f);
        float inter = iw * ih;
        float ap = fmaxf(px2 - px1, 0.f) * fmaxf(py2 - py1, 0.f);
        float ag = fmaxf(gx2 - gx1, 0.f) * fmaxf(gy2 - gy1, 0.f);
        float uni = ap + ag - inter;
        float iou = inter / (uni + 1e-7f);
        float rho2 = (px - gx) * (px - gx) + (py - gy) * (py - gy);
        float cw = fmaxf(px2, gx2) - fminf(px1, gx1);
        float ch = fmaxf(py2, gy2) - fminf(py1, gy1);
        float c2 = cw * cw + ch * ch + 1e-7f;
        float dv = atanf(gw / (gh + 1e-7f)) - atanf(pw / (ph + 1e-7f));
        float v = 0.40528473456935108577f * dv * dv;   // 4/pi^2
        float alpha = v / (1.0f - iou + v + 1e-7f);
        acc_coord += 1.0f - iou + rho2 / c2 + alpha * v;
    }

    // ---- class BCE over (my obj cell, class) pairs ----
    for (int idx = tid; idx < nmy * NC; idx += 256) {
        int i  = idx / NC;
        int cc = idx - i * NC;
        int t  = s_my[i];
        float x = __ldg(pb + (size_t)s_cell[t] * PRED_C + BB * 5 + cc);
        float gflag = ((s_mask[i][cc >> 5] >> (cc & 31)) & 1u) ? 1.0f : 0.0f;
        acc_cls += fmaxf(x, 0.0f) - x * gflag + log1pf(expf(-fabsf(x)));
    }

    // ---- block reduction: shuffle + fixed-order tree ----
    float total = 5.0f * acc_coord + acc_obj + 0.1f * acc_noobj + acc_cls;
    #pragma unroll
    for (int off = 16; off > 0; off >>= 1)
        total += __shfl_down_sync(0xffffffffu, total, off);
    if ((tid & 31) == 0) s_red[tid >> 5] = total;
    __syncthreads();
    if (tid == 0) {
        float v = ((s_red[0] + s_red[1]) + (s_red[2] + s_red[3]))
                + ((s_red[4] + s_red[5]) + (s_red[6] + s_red[7]));
        g_partial[bid] = v;
        __threadfence();
    }
    __syncthreads();

    // ---- last block: fixed-order final reduction (deterministic) ----
    const int nparts = batch * SPLIT;
    __shared__ int s_last;
    if (tid == 0) s_last = (atomicAdd(&g_count, 1) == nparts - 1) ? 1 : 0;
    __syncthreads();
    if (s_last) {
        __shared__ float s_fin[256];
        float v = 0.0f;
        for (int i = tid; i < nparts; i += 256) v += g_partial[i];
        s_fin[tid] = v;
        __syncthreads();
        #pragma unroll
        for (int k = 128; k > 0; k >>= 1) {
            if (tid < k) s_fin[tid] += s_fin[tid + k];
            __syncthreads();
        }
        if (tid == 0) {
            out[0] = s_fin[0] / (float)batch;
            g_count = 0;                     // reset for next graph replay
        }
    }
}

extern "C" void kernel_launch(void* const* d_in, const int* in_sizes, int n_in,
                              void* d_out, int out_size)
{
    const float* pred = (const float*)d_in[0];
    const float* tgt  = (const float*)d_in[1];
    int batch = in_sizes[0] / (SS * PRED_C);
    if (batch > 4096) batch = 4096;
    yolo_loss_kernel<<<batch * SPLIT, 256>>>(pred, tgt, (float*)d_out, batch);
}

// round 4
// speedup vs baseline: 1.0889x; 1.0889x over previous
#include <cuda_runtime.h>

#define S_GRID 28
#define SS 784            // 28*28
#define NC 80
#define BB 2
#define MAXB 50
#define PRED_C 90         // BB*5 + NC
#define NSWEEP 1024       // streaming-reduction blocks for noobj conf

__device__ float g_partial[2048];
__device__ int   g_count = 0;

__global__ __launch_bounds__(256) void yolo_loss_kernel(
    const float* __restrict__ pred,
    const float* __restrict__ tgt,
    float* __restrict__ out,
    int batch)
{
    const int bid = blockIdx.x;
    const int tid = threadIdx.x;
    const float cell = 1.0f / 28.0f;

    float partial = 0.0f;

    if (bid < NSWEEP) {
        // ================= role A: flat noobj confidence sweep =================
        // sum of conf^2 over ALL (batch, cell, box) — target-independent.
        const long total_cells = (long)batch * SS;
        float acc = 0.0f;
        for (long c = (long)bid * 256 + tid; c < total_cells; c += (long)NSWEEP * 256) {
            const float* pp = pred + c * PRED_C;
            float a = __ldg(pp + 4);
            float d = __ldg(pp + 9);
            acc += a * a + d * d;
        }
        partial = 0.1f * acc;
    } else {
        // ================= role B: per-batch target/object losses ==============
        const int b = bid - NSWEEP;
        const float* pb = pred + (size_t)b * SS * PRED_C;

        __shared__ int    s_cell[MAXB];   // -1 = invalid target
        __shared__ float  s_best[MAXB];
        __shared__ int    s_bestj[MAXB];
        __shared__ float4 s_box[MAXB];    // cx_rel, cy_rel, w, h
        __shared__ int    s_cid[MAXB];
        __shared__ unsigned char s_win[MAXB];
        __shared__ int    s_obj[MAXB];
        __shared__ int    s_nobj;
        __shared__ unsigned s_mask[MAXB][3];

        // issue target loads ASAP
        float tcls = -1.f, tcx = 0.f, tcy = 0.f, tw = 0.f, th = 0.f;
        if (tid < MAXB) {
            const float* tt = tgt + ((size_t)b * MAXB + tid) * 5;
            tcls = __ldg(tt + 0); tcx = __ldg(tt + 1); tcy = __ldg(tt + 2);
            tw   = __ldg(tt + 3); th  = __ldg(tt + 4);
        }

        // per-target precompute (dependent: target -> cell -> pred row)
        if (tid < MAXB) {
            if (tcls >= 0.0f) {
                int ci  = min(max((int)tcls, 0), NC - 1);
                int col = min((int)(tcx / cell), S_GRID - 1);
                int row = min((int)(tcy / cell), S_GRID - 1);
                int cc  = row * S_GRID + col;
                s_cell[tid] = cc;
                s_cid[tid]  = ci;
                s_box[tid]  = make_float4(tcx / cell - (float)col,
                                          tcy / cell - (float)row, tw, th);
                const float* pp = pb + (size_t)cc * PRED_C;
                float gx1 = tcx - tw * .5f, gy1 = tcy - th * .5f;
                float gx2 = tcx + tw * .5f, gy2 = tcy + th * .5f;
                float garea = fmaxf(gx2 - gx1, 0.f) * fmaxf(gy2 - gy1, 0.f);
                float iou[2];
                #pragma unroll
                for (int j = 0; j < 2; j++) {
                    float px = (__ldg(pp + 5*j + 0) + (float)col) * cell;
                    float py = (__ldg(pp + 5*j + 1) + (float)row) * cell;
                    float pw = __ldg(pp + 5*j + 2), ph = __ldg(pp + 5*j + 3);
                    float px1 = px - pw * .5f, py1 = py - ph * .5f;
                    float px2 = px + pw * .5f, py2 = py + ph * .5f;
                    float iw = fmaxf(fminf(px2, gx2) - fmaxf(px1, gx1), 0.f);
                    float ih = fmaxf(fminf(py2, gy2) - fmaxf(py1, gy1), 0.f);
                    float inter = iw * ih;
                    float uni = fmaxf(px2 - px1, 0.f) * fmaxf(py2 - py1, 0.f)
                              + garea - inter;
                    iou[j] = inter / (uni + 1e-6f);
                }
                s_bestj[tid] = (iou[1] > iou[0]) ? 1 : 0;   // first-index tie
                s_best[tid]  = fmaxf(iou[0], iou[1]);
            } else {
                s_cell[tid] = -1;
            }
        }
        __syncthreads();

        // winner per cell = first index achieving max best (== scan semantics)
        if (tid < MAXB) {
            bool win = (s_cell[tid] >= 0);
            if (win) {
                int myc = s_cell[tid]; float myb = s_best[tid];
                for (int s = 0; s < MAXB; s++) {
                    if (s == tid || s_cell[s] != myc) continue;
                    float ob = s_best[s];
                    if (ob > myb || (ob == myb && s < tid)) { win = false; break; }
                }
            }
            s_win[tid] = win ? 1 : 0;
        }
        __syncthreads();

        // deterministic compaction (warp 0, two ballots) + class masks
        if (tid < 32) {
            unsigned lt = (1u << tid) - 1u;
            bool p0 = s_win[tid] != 0;
            unsigned m0 = __ballot_sync(0xffffffffu, p0);
            if (p0) s_obj[__popc(m0 & lt)] = tid;
            int c0 = __popc(m0);
            bool p1 = (tid < MAXB - 32) && (s_win[32 + tid] != 0);
            unsigned m1 = __ballot_sync(0xffffffffu, p1);
            if (p1) s_obj[c0 + __popc(m1 & lt)] = 32 + tid;
            if (tid == 0) s_nobj = c0 + __popc(m1);
        }
        __syncthreads();
        const int nobj = s_nobj;

        if (tid < nobj) {
            int t = s_obj[tid];
            int myc = s_cell[t];
            unsigned m0 = 0u, m1 = 0u, m2 = 0u;
            for (int s = 0; s < MAXB; s++) {
                if (s_cell[s] == myc) {
                    int ci = s_cid[s];
                    if (ci < 32)      m0 |= 1u << ci;
                    else if (ci < 64) m1 |= 1u << (ci - 32);
                    else              m2 |= 1u << (ci - 64);
                }
            }
            s_mask[tid][0] = m0; s_mask[tid][1] = m1; s_mask[tid][2] = m2;
        }
        __syncthreads();

        float acc_obj = 0.f, acc_coord = 0.f, acc_cls = 0.f, acc_corr = 0.f;

        // CIoU + obj conf + noobj responsible-box correction
        for (int i = tid; i < nobj; i += 256) {
            int t = s_obj[i];
            int c = s_cell[t];
            const float* pp = pb + (size_t)c * PRED_C;
            int r = s_bestj[t];
            float bx = __ldg(pp + 5*r + 0), by = __ldg(pp + 5*r + 1);
            float bw = __ldg(pp + 5*r + 2), bh = __ldg(pp + 5*r + 3);
            float bc = __ldg(pp + 5*r + 4);
            acc_corr += bc * bc;               // to subtract from noobj sum
            float d = bc - s_best[t];
            acc_obj += d * d;

            int row = c / S_GRID, col = c % S_GRID;
            float4 g = s_box[t];
            float px = (bx + (float)col) * cell, py = (by + (float)row) * cell;
            float pw = fabsf(bw), ph = fabsf(bh);
            float gx = (g.x + (float)col) * cell, gy = (g.y + (float)row) * cell;
            float gw = g.z, gh = g.w;

            float px1 = px - pw * .5f, py1 = py - ph * .5f;
            float px2 = px + pw * .5f, py2 = py + ph * .5f;
            float gx1 = gx - gw * .5f, gy1 = gy - gh * .5f;
            float gx2 = gx + gw * .5f, gy2 = gy + gh * .5f;
            float iw = fmaxf(fminf(px2, gx2) - fmaxf(px1, gx1), 0.f);
            float ih = fmaxf(fminf(py2, gy2) - fmaxf(py1, gy1), 0.f);
            float inter = iw * ih;
            float ap = fmaxf(px2 - px1, 0.f) * fmaxf(py2 - py1, 0.f);
            float ag = fmaxf(gx2 - gx1, 0.f) * fmaxf(gy2 - gy1, 0.f);
            float uni = ap + ag - inter;
            float iou = inter / (uni + 1e-7f);
            float rho2 = (px - gx) * (px - gx) + (py - gy) * (py - gy);
            float cw = fmaxf(px2, gx2) - fminf(px1, gx1);
            float ch = fmaxf(py2, gy2) - fminf(py1, gy1);
            float c2 = cw * cw + ch * ch + 1e-7f;
            float dv = atanf(gw / (gh + 1e-7f)) - atanf(pw / (ph + 1e-7f));
            float v = 0.40528473456935108577f * dv * dv;   // 4/pi^2
            float alpha = v / (1.0f - iou + v + 1e-7f);
            acc_coord += 1.0f - iou + rho2 / c2 + alpha * v;
        }

        // class BCE over (obj cell, class) pairs
        for (int idx = tid; idx < nobj * NC; idx += 256) {
            int i  = idx / NC;
            int cc = idx - i * NC;
            float x = __ldg(pb + (size_t)s_cell[s_obj[i]] * PRED_C + BB * 5 + cc);
            float gflag = ((s_mask[i][cc >> 5] >> (cc & 31)) & 1u) ? 1.0f : 0.0f;
            acc_cls += fmaxf(x, 0.0f) - x * gflag + log1pf(expf(-fabsf(x)));
        }

        partial = 5.0f * acc_coord + acc_obj + acc_cls - 0.1f * acc_corr;
    }

    // ---- block reduction: shuffle + fixed-order tree ----
    __shared__ float s_red[8];
    #pragma unroll
    for (int off = 16; off > 0; off >>= 1)
        partial += __shfl_down_sync(0xffffffffu, partial, off);
    if ((tid & 31) == 0) s_red[tid >> 5] = partial;
    __syncthreads();
    if (tid == 0) {
        float v = ((s_red[0] + s_red[1]) + (s_red[2] + s_red[3]))
                + ((s_red[4] + s_red[5]) + (s_red[6] + s_red[7]));
        g_partial[bid] = v;
        __threadfence();
    }
    __syncthreads();

    // ---- last block: fixed-order final reduction (deterministic) ----
    const int nparts = NSWEEP + batch;
    __shared__ int s_last;
    if (tid == 0) s_last = (atomicAdd(&g_count, 1) == nparts - 1) ? 1 : 0;
    __syncthreads();
    if (s_last) {
        __shared__ float s_fin[256];
        float v = 0.0f;
        for (int i = tid; i < nparts; i += 256) v += g_partial[i];
        s_fin[tid] = v;
        __syncthreads();
        #pragma unroll
        for (int k = 128; k > 0; k >>= 1) {
            if (tid < k) s_fin[tid] += s_fin[tid + k];
            __syncthreads();
        }
        if (tid == 0) {
            out[0] = s_fin[0] / (float)batch;
            g_count = 0;                     // reset for next graph replay
        }
    }
}

extern "C" void kernel_launch(void* const* d_in, const int* in_sizes, int n_in,
                              void* d_out, int out_size)
{
    const float* pred = (const float*)d_in[0];
    const float* tgt  = (const float*)d_in[1];
    int batch = in_sizes[0] / (SS * PRED_C);
    if (batch > 1024) batch = 1024;
    yolo_loss_kernel<<<NSWEEP + batch, 256>>>(pred, tgt, (float*)d_out, batch);
}

// round 5
// speedup vs baseline: 1.3045x; 1.1980x over previous
#include <cuda_runtime.h>

#define S_GRID 28
#define SS 784            // 28*28
#define NC 80
#define BB 2
#define MAXB 50
#define PRED_C 90         // BB*5 + NC
#define NSWEEP 392        // sweep blocks: 4 cells/thread => 8 independent LDGs

__device__ float g_partial[2048];
__device__ int   g_count = 0;

__global__ __launch_bounds__(256) void yolo_loss_kernel(
    const float* __restrict__ pred,
    const float* __restrict__ tgt,
    float* __restrict__ out,
    int batch)
{
    const int bid = blockIdx.x;
    const int tid = threadIdx.x;
    const float cell = 1.0f / 28.0f;

    float partial = 0.0f;

    if (bid >= batch) {
        // ================= role A: flat noobj confidence sweep =================
        // sum conf^2 over ALL (batch, cell, box) — target-independent.
        const long total  = (long)batch * SS;
        const long stride = (long)NSWEEP * 256;
        long c = (long)(bid - batch) * 256 + tid;
        float a0 = 0.f, a1 = 0.f, a2 = 0.f, a3 = 0.f;
        // unrolled x4: 8 independent scattered loads in flight per thread
        for (; c + 3 * stride < total; c += 4 * stride) {
            const float* p0 = pred + (c             ) * PRED_C;
            const float* p1 = pred + (c +     stride) * PRED_C;
            const float* p2 = pred + (c + 2 * stride) * PRED_C;
            const float* p3 = pred + (c + 3 * stride) * PRED_C;
            float x0 = __ldg(p0 + 4), y0 = __ldg(p0 + 9);
            float x1 = __ldg(p1 + 4), y1 = __ldg(p1 + 9);
            float x2 = __ldg(p2 + 4), y2 = __ldg(p2 + 9);
            float x3 = __ldg(p3 + 4), y3 = __ldg(p3 + 9);
            a0 += x0 * x0 + y0 * y0;
            a1 += x1 * x1 + y1 * y1;
            a2 += x2 * x2 + y2 * y2;
            a3 += x3 * x3 + y3 * y3;
        }
        for (; c < total; c += stride) {
            const float* pp = pred + c * PRED_C;
            float x = __ldg(pp + 4), y = __ldg(pp + 9);
            a0 += x * x + y * y;
        }
        partial = 0.1f * ((a0 + a1) + (a2 + a3));
    } else {
        // ================= role B: per-batch target/object losses ==============
        const int b = bid;
        const float* pb = pred + (size_t)b * SS * PRED_C;

        __shared__ int    s_cell[MAXB];   // -1 = invalid target
        __shared__ float  s_best[MAXB];
        __shared__ int    s_bestj[MAXB];
        __shared__ float4 s_box[MAXB];    // cx_rel, cy_rel, w, h
        __shared__ int    s_cid[MAXB];
        __shared__ unsigned char s_win[MAXB];
        __shared__ int    s_obj[MAXB];
        __shared__ int    s_nobj;
        __shared__ unsigned s_mask[MAXB][3];

        // issue target loads ASAP
        float tcls = -1.f, tcx = 0.f, tcy = 0.f, tw = 0.f, th = 0.f;
        if (tid < MAXB) {
            const float* tt = tgt + ((size_t)b * MAXB + tid) * 5;
            tcls = __ldg(tt + 0); tcx = __ldg(tt + 1); tcy = __ldg(tt + 2);
            tw   = __ldg(tt + 3); th  = __ldg(tt + 4);
        }

        // per-target precompute (dependent: target -> cell -> pred row)
        if (tid < MAXB) {
            if (tcls >= 0.0f) {
                int ci  = min(max((int)tcls, 0), NC - 1);
                int col = min((int)(tcx / cell), S_GRID - 1);
                int row = min((int)(tcy / cell), S_GRID - 1);
                int cc  = row * S_GRID + col;
                s_cell[tid] = cc;
                s_cid[tid]  = ci;
                s_box[tid]  = make_float4(tcx / cell - (float)col,
                                          tcy / cell - (float)row, tw, th);
                const float* pp = pb + (size_t)cc * PRED_C;
                float gx1 = tcx - tw * .5f, gy1 = tcy - th * .5f;
                float gx2 = tcx + tw * .5f, gy2 = tcy + th * .5f;
                float garea = fmaxf(gx2 - gx1, 0.f) * fmaxf(gy2 - gy1, 0.f);
                float iou[2];
                #pragma unroll
                for (int j = 0; j < 2; j++) {
                    float px = (__ldg(pp + 5*j + 0) + (float)col) * cell;
                    float py = (__ldg(pp + 5*j + 1) + (float)row) * cell;
                    float pw = __ldg(pp + 5*j + 2), ph = __ldg(pp + 5*j + 3);
                    float px1 = px - pw * .5f, py1 = py - ph * .5f;
                    float px2 = px + pw * .5f, py2 = py + ph * .5f;
                    float iw = fmaxf(fminf(px2, gx2) - fmaxf(px1, gx1), 0.f);
                    float ih = fmaxf(fminf(py2, gy2) - fmaxf(py1, gy1), 0.f);
                    float inter = iw * ih;
                    float uni = fmaxf(px2 - px1, 0.f) * fmaxf(py2 - py1, 0.f)
                              + garea - inter;
                    iou[j] = inter / (uni + 1e-6f);
                }
                s_bestj[tid] = (iou[1] > iou[0]) ? 1 : 0;   // first-index tie
                s_best[tid]  = fmaxf(iou[0], iou[1]);
            } else {
                s_cell[tid] = -1;
            }
        }
        __syncthreads();

        // winner per cell = first index achieving max best (== scan semantics)
        if (tid < MAXB) {
            bool win = (s_cell[tid] >= 0);
            if (win) {
                int myc = s_cell[tid]; float myb = s_best[tid];
                for (int s = 0; s < MAXB; s++) {
                    if (s == tid || s_cell[s] != myc) continue;
                    float ob = s_best[s];
                    if (ob > myb || (ob == myb && s < tid)) { win = false; break; }
                }
            }
            s_win[tid] = win ? 1 : 0;
        }
        __syncthreads();

        // deterministic compaction (warp 0, two ballots)
        if (tid < 32) {
            unsigned lt = (1u << tid) - 1u;
            bool p0 = s_win[tid] != 0;
            unsigned m0 = __ballot_sync(0xffffffffu, p0);
            if (p0) s_obj[__popc(m0 & lt)] = tid;
            int c0 = __popc(m0);
            bool p1 = (tid < MAXB - 32) && (s_win[32 + tid] != 0);
            unsigned m1 = __ballot_sync(0xffffffffu, p1);
            if (p1) s_obj[c0 + __popc(m1 & lt)] = 32 + tid;
            if (tid == 0) s_nobj = c0 + __popc(m1);
        }
        __syncthreads();
        const int nobj = s_nobj;

        // per-winner class masks
        if (tid < nobj) {
            int t = s_obj[tid];
            int myc = s_cell[t];
            unsigned m0 = 0u, m1 = 0u, m2 = 0u;
            for (int s = 0; s < MAXB; s++) {
                if (s_cell[s] == myc) {
                    int ci = s_cid[s];
                    if (ci < 32)      m0 |= 1u << ci;
                    else if (ci < 64) m1 |= 1u << (ci - 32);
                    else              m2 |= 1u << (ci - 64);
                }
            }
            s_mask[tid][0] = m0; s_mask[tid][1] = m1; s_mask[tid][2] = m2;
        }
        __syncthreads();

        float acc_obj = 0.f, acc_coord = 0.f, acc_cls = 0.f, acc_corr = 0.f;

        // CIoU + obj conf + noobj responsible-box correction
        for (int i = tid; i < nobj; i += 256) {
            int t = s_obj[i];
            int c = s_cell[t];
            const float* pp = pb + (size_t)c * PRED_C;
            int r = s_bestj[t];
            float bx = __ldg(pp + 5*r + 0), by = __ldg(pp + 5*r + 1);
            float bw = __ldg(pp + 5*r + 2), bh = __ldg(pp + 5*r + 3);
            float bc = __ldg(pp + 5*r + 4);
            acc_corr += bc * bc;               // to subtract from noobj sum
            float d = bc - s_best[t];
            acc_obj += d * d;

            int row = c / S_GRID, col = c % S_GRID;
            float4 g = s_box[t];
            float px = (bx + (float)col) * cell, py = (by + (float)row) * cell;
            float pw = fabsf(bw), ph = fabsf(bh);
            float gx = (g.x + (float)col) * cell, gy = (g.y + (float)row) * cell;
            float gw = g.z, gh = g.w;

            float px1 = px - pw * .5f, py1 = py - ph * .5f;
            float px2 = px + pw * .5f, py2 = py + ph * .5f;
            float gx1 = gx - gw * .5f, gy1 = gy - gh * .5f;
            float gx2 = gx + gw * .5f, gy2 = gy + gh * .5f;
            float iw = fmaxf(fminf(px2, gx2) - fmaxf(px1, gx1), 0.f);
            float ih = fmaxf(fminf(py2, gy2) - fmaxf(py1, gy1), 0.f);
            float inter = iw * ih;
            float ap = fmaxf(px2 - px1, 0.f) * fmaxf(py2 - py1, 0.f);
            float ag = fmaxf(gx2 - gx1, 0.f) * fmaxf(gy2 - gy1, 0.f);
            float uni = ap + ag - inter;
            float iou = inter / (uni + 1e-7f);
            float rho2 = (px - gx) * (px - gx) + (py - gy) * (py - gy);
            float cw = fmaxf(px2, gx2) - fminf(px1, gx1);
            float ch = fmaxf(py2, gy2) - fminf(py1, gy1);
            float c2 = cw * cw + ch * ch + 1e-7f;
            float dv = atanf(gw / (gh + 1e-7f)) - atanf(pw / (ph + 1e-7f));
            float v = 0.40528473456935108577f * dv * dv;   // 4/pi^2
            float alpha = v / (1.0f - iou + v + 1e-7f);
            acc_coord += 1.0f - iou + rho2 / c2 + alpha * v;
        }

        // class BCE over (obj cell, class) pairs
        for (int idx = tid; idx < nobj * NC; idx += 256) {
            int i  = idx / NC;
            int cc = idx - i * NC;
            float x = __ldg(pb + (size_t)s_cell[s_obj[i]] * PRED_C + BB * 5 + cc);
            float gflag = ((s_mask[i][cc >> 5] >> (cc & 31)) & 1u) ? 1.0f : 0.0f;
            acc_cls += fmaxf(x, 0.0f) - x * gflag + log1pf(__expf(-fabsf(x)));
        }

        partial = 5.0f * acc_coord + acc_obj + acc_cls - 0.1f * acc_corr;
    }

    // ---- block reduction: shuffle + fixed-order tree ----
    __shared__ float s_red[8];
    #pragma unroll
    for (int off = 16; off > 0; off >>= 1)
        partial += __shfl_down_sync(0xffffffffu, partial, off);
    if ((tid & 31) == 0) s_red[tid >> 5] = partial;
    __syncthreads();
    if (tid == 0) {
        float v = ((s_red[0] + s_red[1]) + (s_red[2] + s_red[3]))
                + ((s_red[4] + s_red[5]) + (s_red[6] + s_red[7]));
        g_partial[bid] = v;
        __threadfence();
    }
    __syncthreads();

    // ---- last block: fixed-order final reduction (deterministic) ----
    const int nparts = batch + NSWEEP;
    __shared__ int s_last;
    if (tid == 0) s_last = (atomicAdd(&g_count, 1) == nparts - 1) ? 1 : 0;
    __syncthreads();
    if (s_last) {
        __shared__ float s_fin[256];
        float v = 0.0f;
        for (int i = tid; i < nparts; i += 256) v += g_partial[i];
        s_fin[tid] = v;
        __syncthreads();
        #pragma unroll
        for (int k = 128; k > 0; k >>= 1) {
            if (tid < k) s_fin[tid] += s_fin[tid + k];
            __syncthreads();
        }
        if (tid == 0) {
            out[0] = s_fin[0] / (float)batch;
            g_count = 0;                     // reset for next graph replay
        }
    }
}

extern "C" void kernel_launch(void* const* d_in, const int* in_sizes, int n_in,
                              void* d_out, int out_size)
{
    const float* pred = (const float*)d_in[0];
    const float* tgt  = (const float*)d_in[1];
    int batch = in_sizes[0] / (SS * PRED_C);
    if (batch > 1024) batch = 1024;
    yolo_loss_kernel<<<batch + NSWEEP, 256>>>(pred, tgt, (float*)d_out, batch);
}